// round 12
// baseline (speedup 1.0000x reference)
#include <cuda_runtime.h>

// ---------------- problem constants ----------------
#define NFD    101            // feature dim
#define UNITS  125            // GRU units
#define NG     375            // 3*UNITS
#define NGP    384            // gate-padded weight cols: z@0, r@128, h@256
#define OUT2   202            // 2*NFD
#define OUTP   256            // padded dense cols
#define OUTS   258            // ys smem row stride
#define XSTR   68             // duplicated-activation row stride (16B-aligned for LDS.128)
#define KS_    (UNITS*OUT2)   // 25250
#define NW     (KS_+OUT2)     // 25452
#define GAMMA_ 28
#define LAGT   56             // 70 - 14
#define BATCH  4096
#define TSEQ   70
#define NTHR   512
#define CCONST 0.5413248546129181f   // log(expm1(1))

typedef unsigned long long ull;

// ---------------- scratch (device globals: no allocation allowed) ----------------
__device__ __align__(16) float g_Wk[NFD * NGP];            // (101,384) gate-padded
__device__ __align__(16) float g_U [UNITS * NGP];          // (125,384) gate-padded
__device__ __align__(16) float g_bzr[256];                 // z: b0z+b1z @0, r: b0r+b1r @128
__device__ __align__(16) float g_bxh[128];                 // b0 h-gate
__device__ __align__(16) float g_brh[128];                 // b1 h-gate
__device__ __align__(16) float g_wker [GAMMA_ * UNITS * OUTP]; // 28 x (125,256)
__device__ __align__(16) float g_wbias[GAMMA_ * OUTP];

// ---------------- math helpers ----------------
__device__ __forceinline__ float softplusf_(float x) {
    return (x > 20.f) ? x : log1pf(__expf(x));
}
__device__ __forceinline__ float sigmoidf_(float x) {
    return __fdividef(1.f, 1.f + __expf(-x));
}
__device__ __forceinline__ float tanhf_(float x) {
    float e = __expf(2.f * x);
    return 1.f - __fdividef(2.f, e + 1.f);
}
__device__ __forceinline__ ull ffma2(ull a, ull b, ull c) {
    ull d;
    asm("fma.rn.f32x2 %0, %1, %2, %3;" : "=l"(d) : "l"(a), "l"(b), "l"(c));
    return d;
}
__device__ __forceinline__ float2 unpk(ull v) {
    float2 f;
    asm("mov.b64 {%0, %1}, %2;" : "=f"(f.x), "=f"(f.y) : "l"(v));
    return f;
}

// ---------------- one fused GRU step ----------------
// xd: duplicated activations [NFD][XSTR]; hold/hnew: duplicated hidden [128][XSTR]
// thread (tx<64, ty<8): rows m = ty*4+i (i<4), unit pair (2tx, 2tx+1) in every gate.
// Double-buffered h: reads hold, writes hnew; ONE barrier at the end of the step.
__device__ __forceinline__ void gru_step(const float* __restrict__ xd,
                                         const float* __restrict__ hold,
                                         float* __restrict__ hnew,
                                         int tx, int ty)
{
    ull az[4], ar[4], axh[4], arh[4];
    {
        ull bz  = *reinterpret_cast<const ull*>(g_bzr + 2 * tx);
        ull br  = *reinterpret_cast<const ull*>(g_bzr + 128 + 2 * tx);
        ull bxh = *reinterpret_cast<const ull*>(g_bxh + 2 * tx);
        ull brh = *reinterpret_cast<const ull*>(g_brh + 2 * tx);
        #pragma unroll
        for (int i = 0; i < 4; i++) { az[i] = bz; ar[i] = br; axh[i] = bxh; arh[i] = brh; }
    }
    const float* xrow = xd   + 8 * ty;   // 16B-aligned (XSTR*4=272, 8*ty*4=32)
    const float* hrow = hold + 8 * ty;
    // pass A: x @ Wk  (z,r into shared accs; h-gate into axh)
    {
        const ull* W = reinterpret_cast<const ull*>(g_Wk) + tx;  // row stride 192 ull
        #pragma unroll 4
        for (int k = 0; k < NFD; k++) {
            ull wz = W[k * 192], wr = W[k * 192 + 64], wh = W[k * 192 + 128];
            ulonglong2 xa = *reinterpret_cast<const ulonglong2*>(xrow + k * XSTR);
            ulonglong2 xb = *reinterpret_cast<const ulonglong2*>(xrow + k * XSTR + 4);
            az[0] = ffma2(xa.x, wz, az[0]); ar[0] = ffma2(xa.x, wr, ar[0]); axh[0] = ffma2(xa.x, wh, axh[0]);
            az[1] = ffma2(xa.y, wz, az[1]); ar[1] = ffma2(xa.y, wr, ar[1]); axh[1] = ffma2(xa.y, wh, axh[1]);
            az[2] = ffma2(xb.x, wz, az[2]); ar[2] = ffma2(xb.x, wr, ar[2]); axh[2] = ffma2(xb.x, wh, axh[2]);
            az[3] = ffma2(xb.y, wz, az[3]); ar[3] = ffma2(xb.y, wr, ar[3]); axh[3] = ffma2(xb.y, wh, axh[3]);
        }
    }
    // pass B: h @ U  (z,r continue shared accs; h-gate into arh)
    {
        const ull* W = reinterpret_cast<const ull*>(g_U) + tx;
        #pragma unroll 4
        for (int k = 0; k < UNITS; k++) {
            ull wz = W[k * 192], wr = W[k * 192 + 64], wh = W[k * 192 + 128];
            ulonglong2 xa = *reinterpret_cast<const ulonglong2*>(hrow + k * XSTR);
            ulonglong2 xb = *reinterpret_cast<const ulonglong2*>(hrow + k * XSTR + 4);
            az[0] = ffma2(xa.x, wz, az[0]); ar[0] = ffma2(xa.x, wr, ar[0]); arh[0] = ffma2(xa.x, wh, arh[0]);
            az[1] = ffma2(xa.y, wz, az[1]); ar[1] = ffma2(xa.y, wr, ar[1]); arh[1] = ffma2(xa.y, wh, arh[1]);
            az[2] = ffma2(xb.x, wz, az[2]); ar[2] = ffma2(xb.x, wr, ar[2]); arh[2] = ffma2(xb.x, wh, arh[2]);
            az[3] = ffma2(xb.y, wz, az[3]); ar[3] = ffma2(xb.y, wr, ar[3]); arh[3] = ffma2(xb.y, wh, arh[3]);
        }
    }
    // gate nonlinearities + state update (read hold, write hnew — no intra-step barrier)
    #pragma unroll
    for (int i = 0; i < 4; i++) {
        int m = ty * 4 + i;
        float h0l = hold[(2 * tx)     * XSTR + 2 * m];
        float h0h = hold[(2 * tx + 1) * XSTR + 2 * m];
        float2 z2 = unpk(az[i]),  r2  = unpk(ar[i]);
        float2 x2 = unpk(axh[i]), rh2 = unpk(arh[i]);
        float zl = sigmoidf_(z2.x), zh = sigmoidf_(z2.y);
        float rl = sigmoidf_(r2.x), rr = sigmoidf_(r2.y);
        float hl = tanhf_(x2.x + rl * rh2.x);
        float hh = tanhf_(x2.y + rr * rh2.y);
        float nl = zl * h0l + (1.f - zl) * hl;
        float nh = zh * h0h + (1.f - zh) * hh;
        *reinterpret_cast<float2*>(hnew + (2 * tx)     * XSTR + 2 * m) = make_float2(nl, nl);
        *reinterpret_cast<float2*>(hnew + (2 * tx + 1) * XSTR + 2 * m) = make_float2(nh, nh);
    }
    __syncthreads();   // hnew visible (and xd/hold reads retired) before next step
}

// ---------------- main fused kernel: one CTA owns 32 batch rows ----------------
__global__ void __launch_bounds__(NTHR, 1)
gru_forecast_kernel(const float* __restrict__ inputs,
                    const float* __restrict__ eps_s,
                    float* __restrict__ out)
{
    extern __shared__ float smem[];
    float* xb0 = smem;                        // [NFD][XSTR]
    float* xb1 = xb0 + NFD * XSTR;            // [NFD][XSTR]
    float* hd0 = xb1 + NFD * XSTR;            // [128][XSTR]
    float* hd1 = hd0 + 128 * XSTR;            // [128][XSTR]
    float* ys  = hd1 + 128 * XSTR;            // [32][OUTS]

    const int tid = threadIdx.x;
    const int tx  = tid & 63;
    const int ty  = tid >> 6;
    const int r0  = blockIdx.x * 32;

    for (int idx = tid; idx < 128 * XSTR; idx += NTHR) hd0[idx] = 0.f;

    // preload x for t=0
    for (int idx = tid; idx < 32 * NFD; idx += NTHR) {
        int m = idx / NFD, f = idx - m * NFD;
        float v = inputs[(r0 + m) * (TSEQ * NFD) + f];
        *reinterpret_cast<float2*>(xb0 + f * XSTR + 2 * m) = make_float2(v, v);
    }
    __syncthreads();

    float* hc = hd0;   // current (valid) hidden
    float* hn = hd1;   // next

    // ---- phase 1: 56 warm-up GRU steps, input prefetch overlapped with GEMMs ----
    for (int t = 0; t < LAGT; t++) {
        float* xcur = (t & 1) ? xb1 : xb0;
        float* xnxt = (t & 1) ? xb0 : xb1;
        if (t + 1 < LAGT) {
            for (int idx = tid; idx < 32 * NFD; idx += NTHR) {
                int m = idx / NFD, f = idx - m * NFD;
                float v = inputs[(r0 + m) * (TSEQ * NFD) + (t + 1) * NFD + f];
                *reinterpret_cast<float2*>(xnxt + f * XSTR + 2 * m) = make_float2(v, v);
            }
        }
        gru_step(xcur, hc, hn, tx, ty);
        float* tmp = hc; hc = hn; hn = tmp;
    }

    // ---- phase 2: 28 variational decode steps ----
    for (int step = 0; step < GAMMA_; step++) {
        if (step > 0) {
            const float* es = eps_s + (step - 1) * (BATCH * NFD);
            for (int idx = tid; idx < 32 * NFD; idx += NTHR) {
                int m = idx / NFD, f = idx - m * NFD;
                float v = ys[m * OUTS + f] + ys[m * OUTS + NFD + f] * es[(r0 + m) * NFD + f];
                *reinterpret_cast<float2*>(xb0 + f * XSTR + 2 * m) = make_float2(v, v);
            }
            __syncthreads();
            gru_step(xb0, hc, hn, tx, ty);
            float* tmp = hc; hc = hn; hn = tmp;
        }
        // dense: y = h @ wker[step] + wbias[step]  (cols 2tx,2tx+1 and 128+2tx,129+2tx)
        {
            ull ay0[4], ay1[4];
            ull b0v = *reinterpret_cast<const ull*>(g_wbias + step * OUTP + 2 * tx);
            ull b1v = *reinterpret_cast<const ull*>(g_wbias + step * OUTP + 128 + 2 * tx);
            #pragma unroll
            for (int i = 0; i < 4; i++) { ay0[i] = b0v; ay1[i] = b1v; }
            const ull* W = reinterpret_cast<const ull*>(g_wker + step * (UNITS * OUTP)) + tx;
            const float* hrow = hc + 8 * ty;
            #pragma unroll 4
            for (int k = 0; k < UNITS; k++) {
                ull wa = W[k * 128], wb = W[k * 128 + 64];
                ulonglong2 xa = *reinterpret_cast<const ulonglong2*>(hrow + k * XSTR);
                ulonglong2 xb = *reinterpret_cast<const ulonglong2*>(hrow + k * XSTR + 4);
                ay0[0] = ffma2(xa.x, wa, ay0[0]); ay1[0] = ffma2(xa.x, wb, ay1[0]);
                ay0[1] = ffma2(xa.y, wa, ay0[1]); ay1[1] = ffma2(xa.y, wb, ay1[1]);
                ay0[2] = ffma2(xb.x, wa, ay0[2]); ay1[2] = ffma2(xb.x, wb, ay1[2]);
                ay0[3] = ffma2(xb.y, wa, ay0[3]); ay1[3] = ffma2(xb.y, wb, ay1[3]);
            }
            #pragma unroll
            for (int i = 0; i < 4; i++) {
                float* orow = ys + (ty * 4 + i) * OUTS;
                *reinterpret_cast<ull*>(orow + 2 * tx)       = ay0[i];
                *reinterpret_cast<ull*>(orow + 128 + 2 * tx) = ay1[i];
            }
        }
        __syncthreads();
        // dist params: write output; overwrite ys[:,101:] with scale for next x
        for (int idx = tid; idx < 32 * NFD; idx += NTHR) {
            int m = idx / NFD, f = idx - m * NFD;
            float loc = ys[m * OUTS + f];
            float sc  = 1e-5f + 0.05f * softplusf_(CCONST + ys[m * OUTS + NFD + f]);
            ys[m * OUTS + NFD + f] = sc;
            int ob = (r0 + m) * (GAMMA_ * OUT2) + step * OUT2;
            out[ob + f]       = loc;
            out[ob + NFD + f] = sc;
        }
        __syncthreads();
    }
}

// ---------------- single merged prep kernel ----------------
__global__ void prep_all(const float* __restrict__ Wk, const float* __restrict__ U,
                         const float* __restrict__ b,
                         const float* __restrict__ dvl, const float* __restrict__ dvr,
                         const float* __restrict__ ew0, const float* __restrict__ ew)
{
    const int gs = gridDim.x * blockDim.x;
    const int t0 = blockIdx.x * blockDim.x + threadIdx.x;

    for (int i = t0; i < NFD * NGP; i += gs) {
        int k = i / NGP, n = i - k * NGP;
        int g = n >> 7, c = n & 127;
        g_Wk[i] = (c < UNITS) ? Wk[k * NG + g * UNITS + c] : 0.f;
    }
    for (int i = t0; i < UNITS * NGP; i += gs) {
        int k = i / NGP, n = i - k * NGP;
        int g = n >> 7, c = n & 127;
        g_U[i] = (c < UNITS) ? U[k * NG + g * UNITS + c] : 0.f;
    }
    for (int n = t0; n < 256; n += gs) {
        int g = n >> 7, c = n & 127;
        g_bzr[n] = (c < UNITS) ? (b[g * UNITS + c] + b[NG + g * UNITS + c]) : 0.f;
    }
    for (int c = t0; c < 128; c += gs) {
        g_bxh[c] = (c < UNITS) ? b[2 * UNITS + c] : 0.f;
        g_brh[c] = (c < UNITS) ? b[NG + 2 * UNITS + c] : 0.f;
    }
    for (int i = t0; i < GAMMA_ * UNITS * OUTP; i += gs) {
        int t = i / (UNITS * OUTP);
        int r = i - t * (UNITS * OUTP);
        int u = r / OUTP;
        int o = r - u * OUTP;
        float w = 0.f;
        if (o < OUT2) {
            int j = u * OUT2 + o;
            float e = (t == 0) ? ew0[j] : ew[(t - 1) * NW + j];
            w = dvl[j] + (1e-5f + 0.01f * softplusf_(CCONST + dvr[j])) * e;
        }
        g_wker[i] = w;
    }
    for (int i = t0; i < GAMMA_ * OUTP; i += gs) {
        int t = i / OUTP, o = i - t * OUTP;
        float w = 0.f;
        if (o < OUT2) {
            int j = KS_ + o;
            float e = (t == 0) ? ew0[j] : ew[(t - 1) * NW + j];
            w = dvl[j] + (1e-5f + 0.01f * softplusf_(CCONST + dvr[j])) * e;
        }
        g_wbias[i] = w;
    }
}

// ---------------- launch ----------------
extern "C" void kernel_launch(void* const* d_in, const int* in_sizes, int n_in,
                              void* d_out, int out_size)
{
    const float* inputs = (const float*)d_in[0];
    const float* Wk     = (const float*)d_in[1];
    const float* U      = (const float*)d_in[2];
    const float* b      = (const float*)d_in[3];
    const float* dvl    = (const float*)d_in[4];
    const float* dvr    = (const float*)d_in[5];
    const float* ew0    = (const float*)d_in[6];
    const float* ew     = (const float*)d_in[7];
    const float* es     = (const float*)d_in[8];
    float* out          = (float*)d_out;
    (void)in_sizes; (void)n_in; (void)out_size;

    const int smem_bytes =
        (2 * NFD * XSTR + 2 * 128 * XSTR + 32 * OUTS) * (int)sizeof(float); // 157,600 B
    cudaFuncSetAttribute(gru_forecast_kernel,
                         cudaFuncAttributeMaxDynamicSharedMemorySize, smem_bytes);

    prep_all<<<512, 256>>>(Wk, U, b, dvl, dvr, ew0, ew);
    gru_forecast_kernel<<<BATCH / 32, NTHR, smem_bytes>>>(inputs, es, out);
}

// round 13
// speedup vs baseline: 1.0023x; 1.0023x over previous
#include <cuda_runtime.h>

// ---------------- problem constants ----------------
#define NFD    101            // feature dim
#define UNITS  125            // GRU units
#define NG     375            // 3*UNITS
#define NGP    384            // gate-padded weight cols: z@0, r@128, h@256
#define OUT2   202            // 2*NFD
#define OUTP   256            // padded dense cols
#define OUTS   258            // ys smem row stride
#define XSTR   68             // duplicated-activation row stride (16B-aligned for LDS.128)
#define KS_    (UNITS*OUT2)   // 25250
#define NW     (KS_+OUT2)     // 25452
#define GAMMA_ 28
#define LAGT   56             // 70 - 14
#define BATCH  4096
#define TSEQ   70
#define NTHR   512
#define CCONST 0.5413248546129181f   // log(expm1(1))

typedef unsigned long long ull;

// ---------------- scratch (device globals: no allocation allowed) ----------------
__device__ __align__(16) float g_Wk[NFD * NGP];            // (101,384) gate-padded
__device__ __align__(16) float g_U [UNITS * NGP];          // (125,384) gate-padded
__device__ __align__(16) float g_bzr[256];                 // z: b0z+b1z @0, r: b0r+b1r @128
__device__ __align__(16) float g_bxh[128];                 // b0 h-gate
__device__ __align__(16) float g_brh[128];                 // b1 h-gate
__device__ __align__(16) float g_wker [GAMMA_ * UNITS * OUTP]; // 28 x (125,256)
__device__ __align__(16) float g_wbias[GAMMA_ * OUTP];

// ---------------- math helpers ----------------
__device__ __forceinline__ float softplusf_(float x) {
    return (x > 20.f) ? x : log1pf(__expf(x));
}
__device__ __forceinline__ float sigmoidf_(float x) {
    return __fdividef(1.f, 1.f + __expf(-x));
}
__device__ __forceinline__ float tanhf_(float x) {
    float e = __expf(2.f * x);
    return 1.f - __fdividef(2.f, e + 1.f);
}
__device__ __forceinline__ ull ffma2(ull a, ull b, ull c) {
    ull d;
    asm("fma.rn.f32x2 %0, %1, %2, %3;" : "=l"(d) : "l"(a), "l"(b), "l"(c));
    return d;
}
__device__ __forceinline__ float2 unpk(ull v) {
    float2 f;
    asm("mov.b64 {%0, %1}, %2;" : "=f"(f.x), "=f"(f.y) : "l"(v));
    return f;
}

// ---------------- one fused GRU step ----------------
// xd: duplicated activations [NFD][XSTR]; hold/hnew: duplicated hidden [128][XSTR]
// thread (tx<64, ty<8): rows m = ty*4+i (i<4), unit pair (2tx, 2tx+1) in every gate.
// Double-buffered h: reads hold, writes hnew; ONE barrier at the end of the step.
__device__ __forceinline__ void gru_step(const float* __restrict__ xd,
                                         const float* __restrict__ hold,
                                         float* __restrict__ hnew,
                                         int tx, int ty)
{
    ull az[4], ar[4], axh[4], arh[4];
    {
        ull bz  = *reinterpret_cast<const ull*>(g_bzr + 2 * tx);
        ull br  = *reinterpret_cast<const ull*>(g_bzr + 128 + 2 * tx);
        ull bxh = *reinterpret_cast<const ull*>(g_bxh + 2 * tx);
        ull brh = *reinterpret_cast<const ull*>(g_brh + 2 * tx);
        #pragma unroll
        for (int i = 0; i < 4; i++) { az[i] = bz; ar[i] = br; axh[i] = bxh; arh[i] = brh; }
    }
    const float* xrow = xd   + 8 * ty;   // 16B-aligned (XSTR*4=272, 8*ty*4=32)
    const float* hrow = hold + 8 * ty;
    // pass A: x @ Wk  (z,r into shared accs; h-gate into axh)
    {
        const ull* W = reinterpret_cast<const ull*>(g_Wk) + tx;  // row stride 192 ull
        #pragma unroll 4
        for (int k = 0; k < NFD; k++) {
            ull wz = W[k * 192], wr = W[k * 192 + 64], wh = W[k * 192 + 128];
            ulonglong2 xa = *reinterpret_cast<const ulonglong2*>(xrow + k * XSTR);
            ulonglong2 xb = *reinterpret_cast<const ulonglong2*>(xrow + k * XSTR + 4);
            az[0] = ffma2(xa.x, wz, az[0]); ar[0] = ffma2(xa.x, wr, ar[0]); axh[0] = ffma2(xa.x, wh, axh[0]);
            az[1] = ffma2(xa.y, wz, az[1]); ar[1] = ffma2(xa.y, wr, ar[1]); axh[1] = ffma2(xa.y, wh, axh[1]);
            az[2] = ffma2(xb.x, wz, az[2]); ar[2] = ffma2(xb.x, wr, ar[2]); axh[2] = ffma2(xb.x, wh, axh[2]);
            az[3] = ffma2(xb.y, wz, az[3]); ar[3] = ffma2(xb.y, wr, ar[3]); axh[3] = ffma2(xb.y, wh, axh[3]);
        }
    }
    // pass B: h @ U  (z,r continue shared accs; h-gate into arh)
    {
        const ull* W = reinterpret_cast<const ull*>(g_U) + tx;
        #pragma unroll 4
        for (int k = 0; k < UNITS; k++) {
            ull wz = W[k * 192], wr = W[k * 192 + 64], wh = W[k * 192 + 128];
            ulonglong2 xa = *reinterpret_cast<const ulonglong2*>(hrow + k * XSTR);
            ulonglong2 xb = *reinterpret_cast<const ulonglong2*>(hrow + k * XSTR + 4);
            az[0] = ffma2(xa.x, wz, az[0]); ar[0] = ffma2(xa.x, wr, ar[0]); arh[0] = ffma2(xa.x, wh, arh[0]);
            az[1] = ffma2(xa.y, wz, az[1]); ar[1] = ffma2(xa.y, wr, ar[1]); arh[1] = ffma2(xa.y, wh, arh[1]);
            az[2] = ffma2(xb.x, wz, az[2]); ar[2] = ffma2(xb.x, wr, ar[2]); arh[2] = ffma2(xb.x, wh, arh[2]);
            az[3] = ffma2(xb.y, wz, az[3]); ar[3] = ffma2(xb.y, wr, ar[3]); arh[3] = ffma2(xb.y, wh, arh[3]);
        }
    }
    // gate nonlinearities + state update (read hold, write hnew — no intra-step barrier)
    #pragma unroll
    for (int i = 0; i < 4; i++) {
        int m = ty * 4 + i;
        float h0l = hold[(2 * tx)     * XSTR + 2 * m];
        float h0h = hold[(2 * tx + 1) * XSTR + 2 * m];
        float2 z2 = unpk(az[i]),  r2  = unpk(ar[i]);
        float2 x2 = unpk(axh[i]), rh2 = unpk(arh[i]);
        float zl = sigmoidf_(z2.x), zh = sigmoidf_(z2.y);
        float rl = sigmoidf_(r2.x), rr = sigmoidf_(r2.y);
        float hl = tanhf_(x2.x + rl * rh2.x);
        float hh = tanhf_(x2.y + rr * rh2.y);
        float nl = zl * h0l + (1.f - zl) * hl;
        float nh = zh * h0h + (1.f - zh) * hh;
        *reinterpret_cast<float2*>(hnew + (2 * tx)     * XSTR + 2 * m) = make_float2(nl, nl);
        *reinterpret_cast<float2*>(hnew + (2 * tx + 1) * XSTR + 2 * m) = make_float2(nh, nh);
    }
    __syncthreads();   // hnew visible (and xd/hold reads retired) before next step
}

// ---------------- main fused kernel: one CTA owns 32 batch rows ----------------
__global__ void __launch_bounds__(NTHR, 1)
gru_forecast_kernel(const float* __restrict__ inputs,
                    const float* __restrict__ eps_s,
                    float* __restrict__ out)
{
    extern __shared__ float smem[];
    float* xb0 = smem;                        // [NFD][XSTR]
    float* xb1 = xb0 + NFD * XSTR;            // [NFD][XSTR]
    float* hd0 = xb1 + NFD * XSTR;            // [128][XSTR]
    float* hd1 = hd0 + 128 * XSTR;            // [128][XSTR]
    float* ys  = hd1 + 128 * XSTR;            // [32][OUTS]

    const int tid = threadIdx.x;
    const int tx  = tid & 63;
    const int ty  = tid >> 6;
    const int r0  = blockIdx.x * 32;

    for (int idx = tid; idx < 128 * XSTR; idx += NTHR) hd0[idx] = 0.f;

    // preload x for t=0
    for (int idx = tid; idx < 32 * NFD; idx += NTHR) {
        int m = idx / NFD, f = idx - m * NFD;
        float v = inputs[(r0 + m) * (TSEQ * NFD) + f];
        *reinterpret_cast<float2*>(xb0 + f * XSTR + 2 * m) = make_float2(v, v);
    }
    __syncthreads();

    float* hc = hd0;   // current (valid) hidden
    float* hn = hd1;   // next

    // ---- phase 1: 56 warm-up GRU steps, input prefetch overlapped with GEMMs ----
    for (int t = 0; t < LAGT; t++) {
        float* xcur = (t & 1) ? xb1 : xb0;
        float* xnxt = (t & 1) ? xb0 : xb1;
        if (t + 1 < LAGT) {
            for (int idx = tid; idx < 32 * NFD; idx += NTHR) {
                int m = idx / NFD, f = idx - m * NFD;
                float v = inputs[(r0 + m) * (TSEQ * NFD) + (t + 1) * NFD + f];
                *reinterpret_cast<float2*>(xnxt + f * XSTR + 2 * m) = make_float2(v, v);
            }
        }
        gru_step(xcur, hc, hn, tx, ty);
        float* tmp = hc; hc = hn; hn = tmp;
    }

    // ---- phase 2: 28 variational decode steps ----
    for (int step = 0; step < GAMMA_; step++) {
        if (step > 0) {
            const float* es = eps_s + (step - 1) * (BATCH * NFD);
            for (int idx = tid; idx < 32 * NFD; idx += NTHR) {
                int m = idx / NFD, f = idx - m * NFD;
                float v = ys[m * OUTS + f] + ys[m * OUTS + NFD + f] * es[(r0 + m) * NFD + f];
                *reinterpret_cast<float2*>(xb0 + f * XSTR + 2 * m) = make_float2(v, v);
            }
            __syncthreads();
            gru_step(xb0, hc, hn, tx, ty);
            float* tmp = hc; hc = hn; hn = tmp;
        }
        // dense: y = h @ wker[step] + wbias[step]  (cols 2tx,2tx+1 and 128+2tx,129+2tx)
        {
            ull ay0[4], ay1[4];
            ull b0v = *reinterpret_cast<const ull*>(g_wbias + step * OUTP + 2 * tx);
            ull b1v = *reinterpret_cast<const ull*>(g_wbias + step * OUTP + 128 + 2 * tx);
            #pragma unroll
            for (int i = 0; i < 4; i++) { ay0[i] = b0v; ay1[i] = b1v; }
            const ull* W = reinterpret_cast<const ull*>(g_wker + step * (UNITS * OUTP)) + tx;
            const float* hrow = hc + 8 * ty;
            #pragma unroll 4
            for (int k = 0; k < UNITS; k++) {
                ull wa = W[k * 128], wb = W[k * 128 + 64];
                ulonglong2 xa = *reinterpret_cast<const ulonglong2*>(hrow + k * XSTR);
                ulonglong2 xb = *reinterpret_cast<const ulonglong2*>(hrow + k * XSTR + 4);
                ay0[0] = ffma2(xa.x, wa, ay0[0]); ay1[0] = ffma2(xa.x, wb, ay1[0]);
                ay0[1] = ffma2(xa.y, wa, ay0[1]); ay1[1] = ffma2(xa.y, wb, ay1[1]);
                ay0[2] = ffma2(xb.x, wa, ay0[2]); ay1[2] = ffma2(xb.x, wb, ay1[2]);
                ay0[3] = ffma2(xb.y, wa, ay0[3]); ay1[3] = ffma2(xb.y, wb, ay1[3]);
            }
            #pragma unroll
            for (int i = 0; i < 4; i++) {
                float* orow = ys + (ty * 4 + i) * OUTS;
                *reinterpret_cast<ull*>(orow + 2 * tx)       = ay0[i];
                *reinterpret_cast<ull*>(orow + 128 + 2 * tx) = ay1[i];
            }
        }
        __syncthreads();
        // dist params: write output; overwrite ys[:,101:] with scale for next x
        for (int idx = tid; idx < 32 * NFD; idx += NTHR) {
            int m = idx / NFD, f = idx - m * NFD;
            float loc = ys[m * OUTS + f];
            float sc  = 1e-5f + 0.05f * softplusf_(CCONST + ys[m * OUTS + NFD + f]);
            ys[m * OUTS + NFD + f] = sc;
            int ob = (r0 + m) * (GAMMA_ * OUT2) + step * OUT2;
            out[ob + f]       = loc;
            out[ob + NFD + f] = sc;
        }
        __syncthreads();
    }
}

// ---------------- single merged prep kernel ----------------
__global__ void prep_all(const float* __restrict__ Wk, const float* __restrict__ U,
                         const float* __restrict__ b,
                         const float* __restrict__ dvl, const float* __restrict__ dvr,
                         const float* __restrict__ ew0, const float* __restrict__ ew)
{
    const int gs = gridDim.x * blockDim.x;
    const int t0 = blockIdx.x * blockDim.x + threadIdx.x;

    for (int i = t0; i < NFD * NGP; i += gs) {
        int k = i / NGP, n = i - k * NGP;
        int g = n >> 7, c = n & 127;
        g_Wk[i] = (c < UNITS) ? Wk[k * NG + g * UNITS + c] : 0.f;
    }
    for (int i = t0; i < UNITS * NGP; i += gs) {
        int k = i / NGP, n = i - k * NGP;
        int g = n >> 7, c = n & 127;
        g_U[i] = (c < UNITS) ? U[k * NG + g * UNITS + c] : 0.f;
    }
    for (int n = t0; n < 256; n += gs) {
        int g = n >> 7, c = n & 127;
        g_bzr[n] = (c < UNITS) ? (b[g * UNITS + c] + b[NG + g * UNITS + c]) : 0.f;
    }
    for (int c = t0; c < 128; c += gs) {
        g_bxh[c] = (c < UNITS) ? b[2 * UNITS + c] : 0.f;
        g_brh[c] = (c < UNITS) ? b[NG + 2 * UNITS + c] : 0.f;
    }
    for (int i = t0; i < GAMMA_ * UNITS * OUTP; i += gs) {
        int t = i / (UNITS * OUTP);
        int r = i - t * (UNITS * OUTP);
        int u = r / OUTP;
        int o = r - u * OUTP;
        float w = 0.f;
        if (o < OUT2) {
            int j = u * OUT2 + o;
            float e = (t == 0) ? ew0[j] : ew[(t - 1) * NW + j];
            w = dvl[j] + (1e-5f + 0.01f * softplusf_(CCONST + dvr[j])) * e;
        }
        g_wker[i] = w;
    }
    for (int i = t0; i < GAMMA_ * OUTP; i += gs) {
        int t = i / OUTP, o = i - t * OUTP;
        float w = 0.f;
        if (o < OUT2) {
            int j = KS_ + o;
            float e = (t == 0) ? ew0[j] : ew[(t - 1) * NW + j];
            w = dvl[j] + (1e-5f + 0.01f * softplusf_(CCONST + dvr[j])) * e;
        }
        g_wbias[i] = w;
    }
}

// ---------------- launch ----------------
extern "C" void kernel_launch(void* const* d_in, const int* in_sizes, int n_in,
                              void* d_out, int out_size)
{
    const float* inputs = (const float*)d_in[0];
    const float* Wk     = (const float*)d_in[1];
    const float* U      = (const float*)d_in[2];
    const float* b      = (const float*)d_in[3];
    const float* dvl    = (const float*)d_in[4];
    const float* dvr    = (const float*)d_in[5];
    const float* ew0    = (const float*)d_in[6];
    const float* ew     = (const float*)d_in[7];
    const float* es     = (const float*)d_in[8];
    float* out          = (float*)d_out;
    (void)in_sizes; (void)n_in; (void)out_size;

    const int smem_bytes =
        (2 * NFD * XSTR + 2 * 128 * XSTR + 32 * OUTS) * (int)sizeof(float); // 157,600 B
    cudaFuncSetAttribute(gru_forecast_kernel,
                         cudaFuncAttributeMaxDynamicSharedMemorySize, smem_bytes);

    prep_all<<<512, 256>>>(Wk, U, b, dvl, dvr, ew0, ew);
    gru_forecast_kernel<<<BATCH / 32, NTHR, smem_bytes>>>(inputs, es, out);
}

// round 14
// speedup vs baseline: 1.1037x; 1.1011x over previous
#include <cuda_runtime.h>
#include <cstdint>

// ---------------- problem constants ----------------
#define NFD    101            // feature dim
#define UNITS  125            // GRU units
#define NG     375            // 3*UNITS
#define OUT2   202            // 2*NFD
#define OUTP   256            // padded dense cols
#define OUTS   258            // ys smem row stride
#define XSTR   68             // activation row stride (16B aligned)
#define KTOT   232            // 101 (x) + 125 (h) + 6 pad = 29*8
#define NCG    29             // gate chunks
#define NCD    16             // dense chunks (128 padded k-rows)
#define CHK    8              // k rows per chunk
#define WCH    (CHK*384)      // floats per gate chunk buffer = 3072
#define WCHB   (WCH*4)        // 12288 bytes
#define KS_    (UNITS*OUT2)   // 25250
#define NW     (KS_+OUT2)     // 25452
#define GAMMA_ 28
#define LAGT   56
#define BATCH  4096
#define TSEQ   70
#define NTHR   256
#define CCONST 0.5413248546129181f   // log(expm1(1))

typedef unsigned long long ull;

// ---------------- device-global scratch ----------------
__device__ __align__(16) float g_WU[KTOT * 384];   // rows 0..100 Wk, 101..225 U, 226..231 zero
__device__ __align__(16) float g_bzr[256];         // z bias(b0+b1) @0, r bias @128
__device__ __align__(16) float g_bxh[128];         // b0 h-gate
__device__ __align__(16) float g_brh[128];         // b1 h-gate
__device__ __align__(16) float g_wker[GAMMA_ * 128 * OUTP]; // 28 x (128,256), rows>=125 zero
__device__ __align__(16) float g_wbias[GAMMA_ * OUTP];

// ---------------- math helpers ----------------
__device__ __forceinline__ float softplusf_(float x) {
    return (x > 20.f) ? x : log1pf(__expf(x));
}
__device__ __forceinline__ float sigmoidf_(float x) {
    return __fdividef(1.f, 1.f + __expf(-x));
}
__device__ __forceinline__ float tanhf_(float x) {
    float e = __expf(2.f * x);
    return 1.f - __fdividef(2.f, e + 1.f);
}
__device__ __forceinline__ ull ffma2(ull a, ull b, ull c) {
    ull d;
    asm("fma.rn.f32x2 %0, %1, %2, %3;" : "=l"(d) : "l"(a), "l"(b), "l"(c));
    return d;
}
__device__ __forceinline__ float2 unpk(ull v) {
    float2 f;
    asm("mov.b64 {%0, %1}, %2;" : "=f"(f.x), "=f"(f.y) : "l"(v));
    return f;
}

// ---------------- cp.async helpers ----------------
__device__ __forceinline__ void cp16(uint32_t s, const void* g) {
    asm volatile("cp.async.cg.shared.global [%0], [%1], 16;" :: "r"(s), "l"(g));
}
__device__ __forceinline__ void cp_commit() {
    asm volatile("cp.async.commit_group;" ::: "memory");
}
#define CP_WAIT2() asm volatile("cp.async.wait_group 2;" ::: "memory")

__device__ __forceinline__ void pf_gate(uint32_t wbase, int c, int tid) {
    uint32_t dst = wbase + (uint32_t)(c & 3) * WCHB;
    const float4* src = reinterpret_cast<const float4*>(g_WU + c * WCH);
    cp16(dst + tid * 16,         src + tid);
    cp16(dst + (tid + 256) * 16, src + tid + 256);
    cp16(dst + (tid + 512) * 16, src + tid + 512);
}
__device__ __forceinline__ void pf_dense(uint32_t wbase, const float* wk, int c, int tid) {
    uint32_t dst = wbase + (uint32_t)(c & 3) * WCHB;
    const float4* src = reinterpret_cast<const float4*>(wk + c * (CHK * OUTP));
    cp16(dst + tid * 16,         src + tid);
    cp16(dst + (tid + 256) * 16, src + tid + 256);
}

// pipeline head: guarantee chunk c arrived & all warps past previous compute;
// then prefetch c+3 and ALWAYS commit (empty group keeps wait_group arithmetic uniform)
#define GPIPE(c_, NC_, PF_) do {                      \
    CP_WAIT2(); __syncthreads();                      \
    if ((c_) + 3 < (NC_)) { PF_; }                    \
    cp_commit();                                      \
} while (0)

// ---------------- gate chunk compute ----------------
// MODE 0: h-gate -> axh (pure-x rows); MODE 1: -> arh (pure-h rows); MODE 2: mixed chunk 12
template<int MODE>
__device__ __forceinline__ void gate_chunk(const float* __restrict__ wq, int c,
                                           const float* __restrict__ arow,
                                           ull az[8], ull ar[8], ull axh[8], ull arh[8],
                                           int tx)
{
    const ull* wb = reinterpret_cast<const ull*>(wq + (c & 3) * WCH) + tx;
    const float* ab = arow + (c * CHK) * XSTR;
    #pragma unroll
    for (int kk = 0; kk < CHK; kk++) {
        ull wz = wb[kk * 192], wr = wb[kk * 192 + 64], wh = wb[kk * 192 + 128];
        ulonglong2 a0 = *reinterpret_cast<const ulonglong2*>(ab + kk * XSTR);
        ulonglong2 a1 = *reinterpret_cast<const ulonglong2*>(ab + kk * XSTR + 4);
        ulonglong2 a2 = *reinterpret_cast<const ulonglong2*>(ab + kk * XSTR + 8);
        ulonglong2 a3 = *reinterpret_cast<const ulonglong2*>(ab + kk * XSTR + 12);
        ull av[8] = {a0.x, a0.y, a1.x, a1.y, a2.x, a2.y, a3.x, a3.y};
        const bool isx = (MODE == 0) || (MODE == 2 && (96 + kk) < 101);
        #pragma unroll
        for (int i = 0; i < 8; i++) {
            az[i] = ffma2(av[i], wz, az[i]);
            ar[i] = ffma2(av[i], wr, ar[i]);
            if (isx) axh[i] = ffma2(av[i], wh, axh[i]);
            else     arh[i] = ffma2(av[i], wh, arh[i]);
        }
    }
}

// ---------------- one GRU step (pipelined weights, register gates) ----------------
// ac: combined activations [KTOT][XSTR] (x rows 0..100 current, h rows 101..231 current)
// an: next buffer (h written to rows 101..228; x for next step may be prefetched to 0..100)
__device__ __forceinline__ void gate_step(const float* __restrict__ ac, float* __restrict__ an,
                                          const float* __restrict__ wq, uint32_t wbase,
                                          int tx, int ty, int tid,
                                          const float* __restrict__ xnext_gsrc)
{
    pf_gate(wbase, 0, tid); cp_commit();
    pf_gate(wbase, 1, tid); cp_commit();
    pf_gate(wbase, 2, tid); cp_commit();

    if (xnext_gsrc) {  // phase-1: prefetch next step's x into an rows 0..100
        #pragma unroll 1
        for (int idx = tid; idx < 32 * NFD; idx += NTHR) {
            int m = idx / NFD, f = idx - m * NFD;
            float v = xnext_gsrc[m * (TSEQ * NFD) + f];
            *reinterpret_cast<float2*>(an + f * XSTR + 2 * m) = make_float2(v, v);
        }
    }

    ull az[8], ar[8], axh[8], arh[8];
    {
        ull bz  = *reinterpret_cast<const ull*>(g_bzr + 2 * tx);
        ull br  = *reinterpret_cast<const ull*>(g_bzr + 128 + 2 * tx);
        ull bxh = *reinterpret_cast<const ull*>(g_bxh + 2 * tx);
        ull brh = *reinterpret_cast<const ull*>(g_brh + 2 * tx);
        #pragma unroll
        for (int i = 0; i < 8; i++) { az[i] = bz; ar[i] = br; axh[i] = bxh; arh[i] = brh; }
    }
    const float* arow = ac + 16 * ty;

    #pragma unroll 1
    for (int c = 0; c < 12; c++) {
        GPIPE(c, NCG, pf_gate(wbase, c + 3, tid));
        gate_chunk<0>(wq, c, arow, az, ar, axh, arh, tx);
    }
    {
        GPIPE(12, NCG, pf_gate(wbase, 15, tid));
        gate_chunk<2>(wq, 12, arow, az, ar, axh, arh, tx);
    }
    #pragma unroll 1
    for (int c = 13; c < NCG; c++) {
        GPIPE(c, NCG, pf_gate(wbase, c + 3, tid));
        gate_chunk<1>(wq, c, arow, az, ar, axh, arh, tx);
    }

    // gate nonlinearities; units (2tx, 2tx+1), rows ty*8+i
    #pragma unroll
    for (int i = 0; i < 8; i++) {
        int m = ty * 8 + i;
        float h0l = ac[(101 + 2 * tx)     * XSTR + 2 * m];
        float h0h = ac[(101 + 2 * tx + 1) * XSTR + 2 * m];
        float2 z2 = unpk(az[i]),  r2  = unpk(ar[i]);
        float2 x2 = unpk(axh[i]), rh2 = unpk(arh[i]);
        float zl = sigmoidf_(z2.x), zh = sigmoidf_(z2.y);
        float rl = sigmoidf_(r2.x), rr = sigmoidf_(r2.y);
        float hl = tanhf_(x2.x + rl * rh2.x);
        float hh = tanhf_(x2.y + rr * rh2.y);
        float nl = zl * h0l + (1.f - zl) * hl;
        float nh = zh * h0h + (1.f - zh) * hh;
        *reinterpret_cast<float2*>(an + (101 + 2 * tx)     * XSTR + 2 * m) = make_float2(nl, nl);
        *reinterpret_cast<float2*>(an + (101 + 2 * tx + 1) * XSTR + 2 * m) = make_float2(nh, nh);
    }
    __syncthreads();   // h(next) visible; ac reads retired
}

// ---------------- dense variational GEMM (pipelined) ----------------
__device__ __forceinline__ void dense_step(const float* __restrict__ ac, float* __restrict__ ys,
                                           const float* __restrict__ wq, uint32_t wbase,
                                           const float* __restrict__ wk,
                                           const float* __restrict__ wbia,
                                           int tx, int ty, int tid)
{
    pf_dense(wbase, wk, 0, tid); cp_commit();
    pf_dense(wbase, wk, 1, tid); cp_commit();
    pf_dense(wbase, wk, 2, tid); cp_commit();

    ull ay0[8], ay1[8];
    {
        ull b0v = *reinterpret_cast<const ull*>(wbia + 2 * tx);
        ull b1v = *reinterpret_cast<const ull*>(wbia + 128 + 2 * tx);
        #pragma unroll
        for (int i = 0; i < 8; i++) { ay0[i] = b0v; ay1[i] = b1v; }
    }
    const float* arow = ac + 101 * XSTR + 16 * ty;

    #pragma unroll 1
    for (int c = 0; c < NCD; c++) {
        GPIPE(c, NCD, pf_dense(wbase, wk, c + 3, tid));
        const ull* wb = reinterpret_cast<const ull*>(wq + (c & 3) * WCH) + tx;
        const float* ab = arow + c * CHK * XSTR;
        #pragma unroll
        for (int kk = 0; kk < CHK; kk++) {
            ull wa = wb[kk * 128], wc = wb[kk * 128 + 64];
            ulonglong2 a0 = *reinterpret_cast<const ulonglong2*>(ab + kk * XSTR);
            ulonglong2 a1 = *reinterpret_cast<const ulonglong2*>(ab + kk * XSTR + 4);
            ulonglong2 a2 = *reinterpret_cast<const ulonglong2*>(ab + kk * XSTR + 8);
            ulonglong2 a3 = *reinterpret_cast<const ulonglong2*>(ab + kk * XSTR + 12);
            ull av[8] = {a0.x, a0.y, a1.x, a1.y, a2.x, a2.y, a3.x, a3.y};
            #pragma unroll
            for (int i = 0; i < 8; i++) {
                ay0[i] = ffma2(av[i], wa, ay0[i]);
                ay1[i] = ffma2(av[i], wc, ay1[i]);
            }
        }
    }
    #pragma unroll
    for (int i = 0; i < 8; i++) {
        float* orow = ys + (ty * 8 + i) * OUTS;
        *reinterpret_cast<ull*>(orow + 2 * tx)       = ay0[i];
        *reinterpret_cast<ull*>(orow + 128 + 2 * tx) = ay1[i];
    }
    __syncthreads();
}

// ---------------- main fused kernel: one CTA owns 32 batch rows ----------------
__global__ void __launch_bounds__(NTHR, 1)
gru_forecast_kernel(const float* __restrict__ inputs,
                    const float* __restrict__ eps_s,
                    float* __restrict__ out)
{
    extern __shared__ float smem[];
    float* ad0 = smem;                        // [KTOT][XSTR]
    float* ad1 = ad0 + KTOT * XSTR;           // [KTOT][XSTR]
    float* ys  = ad1 + KTOT * XSTR;           // [32][OUTS]
    float* wq  = ys + 32 * OUTS;              // 4 x WCH weight chunk buffers

    uint32_t wbase;
    asm("{ .reg .u64 t; cvta.to.shared.u64 t, %1; cvt.u32.u64 %0, t; }"
        : "=r"(wbase) : "l"(wq));

    const int tid = threadIdx.x;
    const int tx  = tid & 63;
    const int ty  = tid >> 6;
    const int r0  = blockIdx.x * 32;

    // zero h region (rows 101..231) of both buffers (NaN-safe for zero-weight tail)
    for (int idx = tid; idx < 131 * XSTR; idx += NTHR) {
        ad0[101 * XSTR + idx] = 0.f;
        ad1[101 * XSTR + idx] = 0.f;
    }
    // preload x for t=0 into ad0 rows 0..100
    for (int idx = tid; idx < 32 * NFD; idx += NTHR) {
        int m = idx / NFD, f = idx - m * NFD;
        float v = inputs[(r0 + m) * (TSEQ * NFD) + f];
        *reinterpret_cast<float2*>(ad0 + f * XSTR + 2 * m) = make_float2(v, v);
    }
    __syncthreads();

    float* ac = ad0;
    float* an = ad1;

    // ---- phase 1: 56 warm-up steps; next x prefetched inside gate_step ----
    for (int t = 0; t < LAGT; t++) {
        const float* xn = (t + 1 < LAGT)
            ? inputs + (long)r0 * (TSEQ * NFD) + (t + 1) * NFD : (const float*)0;
        gate_step(ac, an, wq, wbase, tx, ty, tid, xn);
        float* tmp = ac; ac = an; an = tmp;
    }

    // ---- phase 2: 28 variational decode steps ----
    for (int step = 0; step < GAMMA_; step++) {
        if (step > 0) {
            // x = loc + scale * eps  -> ac rows 0..100 (visible at gate_step's first barrier)
            const float* es = eps_s + (long)(step - 1) * (BATCH * NFD);
            for (int idx = tid; idx < 32 * NFD; idx += NTHR) {
                int m = idx / NFD, f = idx - m * NFD;
                float v = ys[m * OUTS + f] + ys[m * OUTS + NFD + f] * es[(r0 + m) * NFD + f];
                *reinterpret_cast<float2*>(ac + f * XSTR + 2 * m) = make_float2(v, v);
            }
            gate_step(ac, an, wq, wbase, tx, ty, tid, (const float*)0);
            float* tmp = ac; ac = an; an = tmp;
        }
        dense_step(ac, ys, wq, wbase,
                   g_wker + (long)step * (128 * OUTP), g_wbias + step * OUTP,
                   tx, ty, tid);
        // dist params: write output; overwrite ys[:,101:] with scale for next x
        for (int idx = tid; idx < 32 * NFD; idx += NTHR) {
            int m = idx / NFD, f = idx - m * NFD;
            float loc = ys[m * OUTS + f];
            float sc  = 1e-5f + 0.05f * softplusf_(CCONST + ys[m * OUTS + NFD + f]);
            ys[m * OUTS + NFD + f] = sc;
            int ob = (r0 + m) * (GAMMA_ * OUT2) + step * OUT2;
            out[ob + f]       = loc;
            out[ob + NFD + f] = sc;
        }
        __syncthreads();
    }
}

// ---------------- single merged prep kernel ----------------
__global__ void prep_all(const float* __restrict__ Wk, const float* __restrict__ U,
                         const float* __restrict__ b,
                         const float* __restrict__ dvl, const float* __restrict__ dvr,
                         const float* __restrict__ ew0, const float* __restrict__ ew)
{
    const int gs = gridDim.x * blockDim.x;
    const int t0 = blockIdx.x * blockDim.x + threadIdx.x;

    // fused gate weights: rows 0..100 = Wk, 101..225 = U, 226..231 = 0; cols gate-padded
    for (int i = t0; i < KTOT * 384; i += gs) {
        int k = i / 384, n = i - k * 384;
        int g = n >> 7, c = n & 127;
        float w = 0.f;
        if (c < UNITS) {
            if (k < NFD)            w = Wk[k * NG + g * UNITS + c];
            else if (k < NFD+UNITS) w = U[(k - NFD) * NG + g * UNITS + c];
        }
        g_WU[i] = w;
    }
    for (int n = t0; n < 256; n += gs) {
        int g = n >> 7, c = n & 127;
        g_bzr[n] = (c < UNITS) ? (b[g * UNITS + c] + b[NG + g * UNITS + c]) : 0.f;
    }
    for (int c = t0; c < 128; c += gs) {
        g_bxh[c] = (c < UNITS) ? b[2 * UNITS + c] : 0.f;
        g_brh[c] = (c < UNITS) ? b[NG + 2 * UNITS + c] : 0.f;
    }
    for (int i = t0; i < GAMMA_ * 128 * OUTP; i += gs) {
        int t = i / (128 * OUTP);
        int r = i - t * (128 * OUTP);
        int u = r / OUTP;
        int o = r - u * OUTP;
        float w = 0.f;
        if (o < OUT2 && u < UNITS) {
            int j = u * OUT2 + o;
            float e = (t == 0) ? ew0[j] : ew[(t - 1) * NW + j];
            w = dvl[j] + (1e-5f + 0.01f * softplusf_(CCONST + dvr[j])) * e;
        }
        g_wker[i] = w;
    }
    for (int i = t0; i < GAMMA_ * OUTP; i += gs) {
        int t = i / OUTP, o = i - t * OUTP;
        float w = 0.f;
        if (o < OUT2) {
            int j = KS_ + o;
            float e = (t == 0) ? ew0[j] : ew[(t - 1) * NW + j];
            w = dvl[j] + (1e-5f + 0.01f * softplusf_(CCONST + dvr[j])) * e;
        }
        g_wbias[i] = w;
    }
}

// ---------------- launch ----------------
extern "C" void kernel_launch(void* const* d_in, const int* in_sizes, int n_in,
                              void* d_out, int out_size)
{
    const float* inputs = (const float*)d_in[0];
    const float* Wk     = (const float*)d_in[1];
    const float* U      = (const float*)d_in[2];
    const float* b      = (const float*)d_in[3];
    const float* dvl    = (const float*)d_in[4];
    const float* dvr    = (const float*)d_in[5];
    const float* ew0    = (const float*)d_in[6];
    const float* ew     = (const float*)d_in[7];
    const float* es     = (const float*)d_in[8];
    float* out          = (float*)d_out;
    (void)in_sizes; (void)n_in; (void)out_size;

    const int smem_bytes =
        (2 * KTOT * XSTR + 32 * OUTS + 4 * WCH) * (int)sizeof(float); // 208,384 B
    cudaFuncSetAttribute(gru_forecast_kernel,
                         cudaFuncAttributeMaxDynamicSharedMemorySize, smem_bytes);

    prep_all<<<512, 256>>>(Wk, U, b, dvl, dvr, ew0, ew);
    gru_forecast_kernel<<<BATCH / 32, NTHR, smem_bytes>>>(inputs, es, out);
}